// round 5
// baseline (speedup 1.0000x reference)
#include <cuda_runtime.h>
#include <math.h>

// ---------------- problem constants ----------------
constexpr int B = 2, V = 3, G = 2, NH = 8, C = 128;
constexpr int CPG = C / G;       // 64
constexpr int CH  = C / NH;      // 16
constexpr int HPG = NH / G;      // 4
constexpr int Hq = 32, Wq = 32, M = Hq * Wq;   // 1024
constexpr int D = 4;
constexpr int Hk = Hq / 2, Wk = Wq * D;        // 16, 128
constexpr int NS = Hk * Wk;                    // 2048
constexpr int Hi = 64, Wi = 64;
constexpr int RH = Hq * 2 - 1;   // 63
constexpr int RW = Wq * D * 2 - 1; // 255
constexpr float SCALE = 0.25f;
constexpr float OFR = 5.0f;
constexpr float EPS = 1e-5f;

// packed f32x2 helpers (FFMA2 — only reachable via explicit PTX)
#define FMA2(d, a, b, c) asm("fma.rn.f32x2 %0, %1, %2, %3;" : "=l"(d) : "l"(a), "l"(b), "l"(c))
#define MUL2(d, a, b)    asm("mul.rn.f32x2 %0, %1, %2;"     : "=l"(d) : "l"(a), "l"(b))
#define PACK2(d, lo, hi) asm("mov.b64 %0, {%1, %2};"        : "=l"(d) : "f"(lo), "f"(hi))
#define UNPACK2(lo, hi, v) asm("mov.b64 {%0, %1}, %2;"      : "=f"(lo), "=f"(hi) : "l"(v))

// ---------------- scratch (static device globals; no allocation) -------------
__device__ float g_rwo[V][B * G][NS][2];
__device__ float g_xs[V][B][C][NS];
__device__ float g_k[V][B][C][NS];
__device__ float g_v[V][B][C][NS];
__device__ float g_outcat[B][V * C][M];

// =====================================================================
// Kernel 1: offset net. ONE THREAD PER PIXEL. (unchanged — correct)
// =====================================================================
__global__ __launch_bounds__(256) void k_offset(
    const float* __restrict__ query,
    const float* __restrict__ refpts,
    const float* __restrict__ w1,
    const float* __restrict__ b1,
    const float* __restrict__ lng,
    const float* __restrict__ lnb,
    const float* __restrict__ w2)
{
    int pix = blockIdx.x * 256 + threadIdx.x;
    int bg = blockIdx.y, vi = blockIdx.z;
    int b = bg / G, g = bg % G;
    int y = pix >> 5, x = pix & 31;

    const float* W1 = w1 + vi * 256;
    const float* B1 = b1 + vi * 256;
    const float* LG = lng + vi * 256;
    const float* LB = lnb + vi * 256;
    const float* W2 = w2 + vi * 4 * 256;

    float s = 0.f, ss = 0.f;
    for (int c = 0; c < CPG; c++) {
        float qv = query[((b * C + g * CPG + c) * Hq + y) * Wq + x];
#pragma unroll
        for (int d = 0; d < 4; d++) {
            int cd = c * 4 + d;
            float hv = qv * W1[cd] + B1[cd];
            s += hv; ss += hv * hv;
        }
    }
    float mu  = s * (1.f / 256.f);
    float var = ss * (1.f / 256.f) - mu * mu;
    float rs  = rsqrtf(var + EPS);

    float po[4] = {0.f, 0.f, 0.f, 0.f};
    for (int c = 0; c < CPG; c++) {
        float qv = query[((b * C + g * CPG + c) * Hq + y) * Wq + x];
#pragma unroll
        for (int d = 0; d < 4; d++) {
            int cd = c * 4 + d;
            float hv = qv * W1[cd] + B1[cd];
            float hn = (hv - mu) * rs * LG[cd] + LB[cd];
            float ge = 0.5f * hn * (1.f + erff(hn * 0.70710678118654752f));
#pragma unroll
            for (int d2 = 0; d2 < 4; d2++)
                po[d2] += ge * W2[d2 * 256 + cd];
        }
    }

    int p = y & 1, hk = y >> 1;
    float scl = (p == 0) ? (OFR / (float)(Hk - 1)) : (OFR / (float)(Wk - 1));
#pragma unroll
    for (int d = 0; d < 4; d++) {
        int wk = x * 4 + d;
        float rv = refpts[(((b * V + vi) * Hk + hk) * Wk + wk) * 2 + (1 - p)];
        g_rwo[vi][bg][hk * Wk + wk][p] = tanhf(po[d]) * scl + rv;
    }
}

// =====================================================================
// Kernel 2: bilinear grid-sample of x (unchanged)
// =====================================================================
__global__ __launch_bounds__(256) void k_sample(const float* __restrict__ x)
{
    int cc = threadIdx.x & 63;
    int nsub = threadIdx.x >> 6;
    int n = blockIdx.x * 4 + nsub;
    int bg = blockIdx.y, vi = blockIdx.z;
    int b = bg / G, g = bg % G;

    float r0 = g_rwo[vi][bg][n][0];
    float r1 = g_rwo[vi][bg][n][1];
    float yp = (r0 + 1.f) * 0.5f * (float)(Hi - 1);
    float xp = (r1 + 1.f) * 0.5f * (float)(Wi - 1);
    float y0f = floorf(yp), x0f = floorf(xp);
    float fy = yp - y0f, fx = xp - x0f;
    int y0 = (int)y0f, x0 = (int)x0f;

    float wy0 = (y0     >= 0 && y0     <= Hi - 1) ? (1.f - fy) : 0.f;
    float wy1 = (y0 + 1 >= 0 && y0 + 1 <= Hi - 1) ? fy         : 0.f;
    float wx0 = (x0     >= 0 && x0     <= Wi - 1) ? (1.f - fx) : 0.f;
    float wx1 = (x0 + 1 >= 0 && x0 + 1 <= Wi - 1) ? fx         : 0.f;
    int iy0 = min(max(y0, 0), Hi - 1), iy1 = min(max(y0 + 1, 0), Hi - 1);
    int ix0 = min(max(x0, 0), Wi - 1), ix1 = min(max(x0 + 1, 0), Wi - 1);

    const float* img = x + (size_t)((b * V + vi) * C + g * CPG + cc) * (Hi * Wi);
    float val = wy0 * wx0 * img[iy0 * Wi + ix0]
              + wy0 * wx1 * img[iy0 * Wi + ix1]
              + wy1 * wx0 * img[iy1 * Wi + ix0]
              + wy1 * wx1 * img[iy1 * Wi + ix1];
    g_xs[vi][b][g * CPG + cc][n] = val;
}

// =====================================================================
// Kernel 3: K/V projection (unchanged)
// =====================================================================
__global__ __launch_bounds__(256) void k_proj(
    const float* __restrict__ kw, const float* __restrict__ kb,
    const float* __restrict__ vw, const float* __restrict__ vb)
{
    int n  = blockIdx.x * 256 + threadIdx.x;
    int o0 = blockIdx.y * 8;
    int z  = blockIdx.z;
    int kv = z & 1, b = (z >> 1) & 1, vi = z >> 2;
    const float* w    = kv ? vw : kw;
    const float* bias = kv ? vb : kb;

    __shared__ float sW[8][C];
    for (int idx = threadIdx.x; idx < 8 * C; idx += 256)
        sW[idx >> 7][idx & 127] = w[(o0 + (idx >> 7)) * C + (idx & 127)];
    __syncthreads();

    float acc[8];
#pragma unroll
    for (int oo = 0; oo < 8; oo++) acc[oo] = bias[o0 + oo];

    const float* xs = &g_xs[vi][b][0][0];
    for (int c = 0; c < C; c++) {
        float xv = xs[c * NS + n];
#pragma unroll
        for (int oo = 0; oo < 8; oo++) acc[oo] += sW[oo][c] * xv;
    }
    float* dst = kv ? &g_v[vi][b][0][0] : &g_k[vi][b][0][0];
#pragma unroll
    for (int oo = 0; oo < 8; oo++) dst[(o0 + oo) * NS + n] = acc[oo];
}

// =====================================================================
// Kernel 4: attention, 2-query tiling + packed f32x2 hot loops.
// smem K/V layout [n][c] with pitch 18 (72B rows: 8B-aligned, conflict-free
// LDS.64). QK/PV done as channel-pair FFMA2.
// =====================================================================
constexpr int KP = 18;   // row pitch in floats

__global__ __launch_bounds__(256) void k_attn(
    const float* __restrict__ query,
    const float* __restrict__ rpe_table)
{
    int warp = threadIdx.x >> 5, lane = threadIdx.x & 31, tid = threadIdx.x;
    int vi = blockIdx.z;
    int bh = blockIdx.y;
    int b = bh / NH, h = bh % NH;
    int g = h / HPG;
    int bg = b * G + g;

    int mp = blockIdx.x * 8 + warp;      // pair index 0..511
    int i0 = (mp >> 5) * 2;
    int j  = mp & 31;
    int m0 = i0 * 32 + j;
    int m1 = m0 + 32;

    __shared__ float sK[256][KP];
    __shared__ float sV[256][KP];
    __shared__ float sR0[256];
    __shared__ float sR1[256];

    // q packed as channel pairs
    unsigned long long qp0[CH / 2], qp1[CH / 2];
#pragma unroll
    for (int cp = 0; cp < CH / 2; cp++) {
        float a0 = query[(b * C + h * CH + 2 * cp) * M + m0];
        float b0 = query[(b * C + h * CH + 2 * cp + 1) * M + m0];
        float a1 = query[(b * C + h * CH + 2 * cp) * M + m1];
        float b1v = query[(b * C + h * CH + 2 * cp + 1) * M + m1];
        PACK2(qp0[cp], a0, b0);
        PACK2(qp1[cp], a1, b1v);
    }

    const float* rpe = rpe_table + h * RH * RW;
    const float* kbase = &g_k[vi][b][h * CH][0];
    const float* vbase = &g_v[vi][b][h * CH][0];

    float ml0 = -1e30f, ll0 = 0.f, ml1 = -1e30f, ll1 = 0.f;
    unsigned long long ap0[CH / 2], ap1[CH / 2];
    unsigned long long zero2; { PACK2(zero2, 0.f, 0.f); }
#pragma unroll
    for (int cp = 0; cp < CH / 2; cp++) { ap0[cp] = zero2; ap1[cp] = zero2; }

    float ybase = 15.5f + (float)i0;
    float xbase = 63.5f + (127.0f / 31.0f) * (float)j;

    for (int t = 0; t < NS / 256; t++) {
        __syncthreads();
        // fill sK/sV transposed: [n][c], coalesced global reads
        for (int idx = tid; idx < CH * 256; idx += 256) {
            int c = idx >> 8, n = idx & 255;
            sK[n][c] = kbase[c * NS + t * 256 + n];
            sV[n][c] = vbase[c * NS + t * 256 + n];
        }
        {
            float2 rv = ((const float2*)&g_rwo[vi][bg][t * 256][0])[tid];
            sR0[tid] = rv.x;
            sR1[tid] = rv.y;
        }
        __syncthreads();

#pragma unroll 1
        for (int ch = 0; ch < 8; ch++) {
            int nl = ch * 32 + lane;

            // QK via packed channel pairs
            const unsigned long long* krow =
                (const unsigned long long*)&sK[nl][0];
            unsigned long long s0p = zero2, s1p = zero2;
#pragma unroll
            for (int cp = 0; cp < CH / 2; cp++) {
                unsigned long long kk = krow[cp];
                FMA2(s0p, qp0[cp], kk, s0p);
                FMA2(s1p, qp1[cp], kk, s1p);
            }
            float s0a, s0b, s1a, s1b;
            UNPACK2(s0a, s0b, s0p);
            UNPACK2(s1a, s1b, s1p);
            float s0 = s0a + s0b, s1 = s1a + s1b;

            // --- shared bilinear rpe for the query pair ---
            float r0v = sR0[nl], r1v = sR1[nl];
            float xp = xbase - 63.5f * r1v;
            float x0f = floorf(xp);
            float fx = xp - x0f;
            int x0 = (int)x0f;
            float wx0 = (x0     >= 0 && x0     <= RW - 1) ? (1.f - fx) : 0.f;
            float wx1 = (x0 + 1 >= 0 && x0 + 1 <= RW - 1) ? fx         : 0.f;
            int ix0 = min(max(x0, 0), RW - 1), ix1 = min(max(x0 + 1, 0), RW - 1);

            float yp = ybase - 15.5f * r0v;
            float y0f = floorf(yp);
            float fy = yp - y0f;
            int y0 = (int)y0f;
            bool v0 = (y0     >= 0) && (y0     <= RH - 1);
            bool v1 = (y0 + 1 >= 0) && (y0 + 1 <= RH - 1);
            bool v2 = (y0 + 2 >= 0) && (y0 + 2 <= RH - 1);
            int cr0 = min(max(y0,     0), RH - 1);
            int cr1 = min(max(y0 + 1, 0), RH - 1);
            int cr2 = min(max(y0 + 2, 0), RH - 1);

            const float* p0r = rpe + cr0 * RW;
            const float* p1r = rpe + cr1 * RW;
            const float* p2r = rpe + cr2 * RW;
            float rc0 = wx0 * p0r[ix0] + wx1 * p0r[ix1];
            float rc1 = wx0 * p1r[ix0] + wx1 * p1r[ix1];
            float rc2 = wx0 * p2r[ix0] + wx1 * p2r[ix1];

            float wyA0 = v0 ? (1.f - fy) : 0.f;
            float wyA1 = v1 ? fy         : 0.f;
            float wyB0 = v1 ? (1.f - fy) : 0.f;
            float wyB1 = v2 ? fy         : 0.f;

            s0 = s0 * SCALE + wyA0 * rc0 + wyA1 * rc1;
            s1 = s1 * SCALE + wyB0 * rc1 + wyB1 * rc2;

            // --- per-lane online softmax (packed rescale) ---
            if (s0 > ml0) {
                float sc = __expf(ml0 - s0);
                ll0 *= sc;
                unsigned long long scp; PACK2(scp, sc, sc);
#pragma unroll
                for (int cp = 0; cp < CH / 2; cp++) MUL2(ap0[cp], ap0[cp], scp);
                ml0 = s0;
            }
            float p0 = __expf(s0 - ml0);
            ll0 += p0;
            if (s1 > ml1) {
                float sc = __expf(ml1 - s1);
                ll1 *= sc;
                unsigned long long scp; PACK2(scp, sc, sc);
#pragma unroll
                for (int cp = 0; cp < CH / 2; cp++) MUL2(ap1[cp], ap1[cp], scp);
                ml1 = s1;
            }
            float p1 = __expf(s1 - ml1);
            ll1 += p1;

            unsigned long long p0p, p1p;
            PACK2(p0p, p0, p0);
            PACK2(p1p, p1, p1);
            const unsigned long long* vrow =
                (const unsigned long long*)&sV[nl][0];
#pragma unroll
            for (int cp = 0; cp < CH / 2; cp++) {
                unsigned long long vvp = vrow[cp];
                FMA2(ap0[cp], p0p, vvp, ap0[cp]);
                FMA2(ap1[cp], p1p, vvp, ap1[cp]);
            }
        }
    }

    // cross-lane reductions
    float gm0 = ml0, gm1 = ml1;
#pragma unroll
    for (int o = 16; o; o >>= 1) {
        gm0 = fmaxf(gm0, __shfl_xor_sync(0xffffffffu, gm0, o));
        gm1 = fmaxf(gm1, __shfl_xor_sync(0xffffffffu, gm1, o));
    }
    float f0 = __expf(ml0 - gm0), f1 = __expf(ml1 - gm1);
    float ls0 = ll0 * f0, ls1 = ll1 * f1;
#pragma unroll
    for (int o = 16; o; o >>= 1) {
        ls0 += __shfl_xor_sync(0xffffffffu, ls0, o);
        ls1 += __shfl_xor_sync(0xffffffffu, ls1, o);
    }
    float inv0 = 1.f / ls0, inv1 = 1.f / ls1;

#pragma unroll
    for (int cp = 0; cp < CH / 2; cp++) {
        float a0, b0, a1, b1v;
        UNPACK2(a0, b0, ap0[cp]);
        UNPACK2(a1, b1v, ap1[cp]);
        float o00 = a0 * f0, o01 = b0 * f0;
        float o10 = a1 * f1, o11 = b1v * f1;
#pragma unroll
        for (int q = 16; q; q >>= 1) {
            o00 += __shfl_xor_sync(0xffffffffu, o00, q);
            o01 += __shfl_xor_sync(0xffffffffu, o01, q);
            o10 += __shfl_xor_sync(0xffffffffu, o10, q);
            o11 += __shfl_xor_sync(0xffffffffu, o11, q);
        }
        if (lane == 0) {
            g_outcat[b][vi * C + h * CH + 2 * cp][m0]     = o00 * inv0;
            g_outcat[b][vi * C + h * CH + 2 * cp + 1][m0] = o01 * inv0;
            g_outcat[b][vi * C + h * CH + 2 * cp][m1]     = o10 * inv1;
            g_outcat[b][vi * C + h * CH + 2 * cp + 1][m1] = o11 * inv1;
        }
    }
}

// =====================================================================
// Kernel 5: output projection (unchanged)
// =====================================================================
__global__ __launch_bounds__(256) void k_out(
    const float* __restrict__ ow, const float* __restrict__ ob,
    float* __restrict__ out)
{
    int mm = blockIdx.x * 256 + threadIdx.x;
    int o0 = blockIdx.y * 8;
    int b  = blockIdx.z;

    __shared__ float sW[8][V * C];
    for (int idx = threadIdx.x; idx < 8 * V * C; idx += 256)
        sW[idx / (V * C)][idx % (V * C)] = ow[(o0 + idx / (V * C)) * (V * C) + (idx % (V * C))];
    __syncthreads();

    float acc[8];
#pragma unroll
    for (int oo = 0; oo < 8; oo++) acc[oo] = ob[o0 + oo];

    const float* src = &g_outcat[b][0][0];
    for (int c = 0; c < V * C; c++) {
        float xv = src[c * M + mm];
#pragma unroll
        for (int oo = 0; oo < 8; oo++) acc[oo] += sW[oo][c] * xv;
    }
#pragma unroll
    for (int oo = 0; oo < 8; oo++)
        out[(b * C + o0 + oo) * M + mm] = acc[oo];
}

// =====================================================================
extern "C" void kernel_launch(void* const* d_in, const int* in_sizes, int n_in,
                              void* d_out, int out_size)
{
    const float *x, *query, *refpts, *off_w1, *off_b1, *off_ln_g, *off_ln_b,
                *off_w2, *k_w, *k_b, *v_w, *v_b, *out_w, *out_b, *rpe;

    if (n_in >= 15 && in_sizes[0] == 3145728) {
        x        = (const float*)d_in[0];
        query    = (const float*)d_in[1];
        refpts   = (const float*)d_in[2];
        off_w1   = (const float*)d_in[3];
        off_b1   = (const float*)d_in[4];
        off_ln_g = (const float*)d_in[5];
        off_ln_b = (const float*)d_in[6];
        off_w2   = (const float*)d_in[7];
        k_w      = (const float*)d_in[8];
        k_b      = (const float*)d_in[9];
        v_w      = (const float*)d_in[10];
        v_b      = (const float*)d_in[11];
        out_w    = (const float*)d_in[12];
        out_b    = (const float*)d_in[13];
        rpe      = (const float*)d_in[14];
    } else {
        k_b      = (const float*)d_in[0];
        k_w      = (const float*)d_in[1];
        off_b1   = (const float*)d_in[2];
        off_ln_b = (const float*)d_in[3];
        off_ln_g = (const float*)d_in[4];
        off_w1   = (const float*)d_in[5];
        off_w2   = (const float*)d_in[6];
        out_b    = (const float*)d_in[7];
        out_w    = (const float*)d_in[8];
        query    = (const float*)d_in[9];
        refpts   = (const float*)d_in[10];
        rpe      = (const float*)d_in[11];
        v_b      = (const float*)d_in[12];
        v_w      = (const float*)d_in[13];
        x        = (const float*)d_in[14];
    }
    float* out = (float*)d_out;

    k_offset<<<dim3(M / 256, B * G, V), 256>>>(query, refpts, off_w1, off_b1,
                                               off_ln_g, off_ln_b, off_w2);
    k_sample<<<dim3(NS / 4, B * G, V), 256>>>(x);
    k_proj<<<dim3(NS / 256, C / 8, V * B * 2), 256>>>(k_w, k_b, v_w, v_b);
    k_attn<<<dim3(M / 2 / 8, B * NH, V), 256>>>(query, rpe);
    k_out<<<dim3(M / 256, C / 8, B), 256>>>(out_w, out_b, out);
}

// round 6
// speedup vs baseline: 1.3811x; 1.3811x over previous
#include <cuda_runtime.h>
#include <math.h>

// ---------------- problem constants ----------------
constexpr int B = 2, V = 3, G = 2, NH = 8, C = 128;
constexpr int CPG = C / G;       // 64
constexpr int CH  = C / NH;      // 16
constexpr int HPG = NH / G;      // 4
constexpr int Hq = 32, Wq = 32, M = Hq * Wq;   // 1024
constexpr int D = 4;
constexpr int Hk = Hq / 2, Wk = Wq * D;        // 16, 128
constexpr int NS = Hk * Wk;                    // 2048
constexpr int Hi = 64, Wi = 64;
constexpr int RH = Hq * 2 - 1;   // 63
constexpr int RW = Wq * D * 2 - 1; // 255
constexpr float SCALE = 0.25f;
constexpr float OFR = 5.0f;
constexpr float EPS = 1e-5f;

// packed f32x2 helpers
#define FMA2(d, a, b, c) asm("fma.rn.f32x2 %0, %1, %2, %3;" : "=l"(d) : "l"(a), "l"(b), "l"(c))
#define MUL2(d, a, b)    asm("mul.rn.f32x2 %0, %1, %2;"     : "=l"(d) : "l"(a), "l"(b))
#define PACK2(d, lo, hi) asm("mov.b64 %0, {%1, %2};"        : "=l"(d) : "f"(lo), "f"(hi))
#define UNPACK2(lo, hi, v) asm("mov.b64 {%0, %1}, %2;"      : "=f"(lo), "=f"(hi) : "l"(v))

// ---------------- scratch ----------------
__device__ float g_rwo[V][B * G][NS][2];
__device__ float g_xs[V][B][C][NS];
__device__ float g_k[V][B][C][NS];
__device__ float g_v[V][B][C][NS];
__device__ float g_outcat[B][V * C][M];

// =====================================================================
// Kernel 1: offset net (unchanged — correct)
// =====================================================================
__global__ __launch_bounds__(256) void k_offset(
    const float* __restrict__ query,
    const float* __restrict__ refpts,
    const float* __restrict__ w1,
    const float* __restrict__ b1,
    const float* __restrict__ lng,
    const float* __restrict__ lnb,
    const float* __restrict__ w2)
{
    int pix = blockIdx.x * 256 + threadIdx.x;
    int bg = blockIdx.y, vi = blockIdx.z;
    int b = bg / G, g = bg % G;
    int y = pix >> 5, x = pix & 31;

    const float* W1 = w1 + vi * 256;
    const float* B1 = b1 + vi * 256;
    const float* LG = lng + vi * 256;
    const float* LB = lnb + vi * 256;
    const float* W2 = w2 + vi * 4 * 256;

    float s = 0.f, ss = 0.f;
    for (int c = 0; c < CPG; c++) {
        float qv = query[((b * C + g * CPG + c) * Hq + y) * Wq + x];
#pragma unroll
        for (int d = 0; d < 4; d++) {
            int cd = c * 4 + d;
            float hv = qv * W1[cd] + B1[cd];
            s += hv; ss += hv * hv;
        }
    }
    float mu  = s * (1.f / 256.f);
    float var = ss * (1.f / 256.f) - mu * mu;
    float rs  = rsqrtf(var + EPS);

    float po[4] = {0.f, 0.f, 0.f, 0.f};
    for (int c = 0; c < CPG; c++) {
        float qv = query[((b * C + g * CPG + c) * Hq + y) * Wq + x];
#pragma unroll
        for (int d = 0; d < 4; d++) {
            int cd = c * 4 + d;
            float hv = qv * W1[cd] + B1[cd];
            float hn = (hv - mu) * rs * LG[cd] + LB[cd];
            float ge = 0.5f * hn * (1.f + erff(hn * 0.70710678118654752f));
#pragma unroll
            for (int d2 = 0; d2 < 4; d2++)
                po[d2] += ge * W2[d2 * 256 + cd];
        }
    }

    int p = y & 1, hk = y >> 1;
    float scl = (p == 0) ? (OFR / (float)(Hk - 1)) : (OFR / (float)(Wk - 1));
#pragma unroll
    for (int d = 0; d < 4; d++) {
        int wk = x * 4 + d;
        float rv = refpts[(((b * V + vi) * Hk + hk) * Wk + wk) * 2 + (1 - p)];
        g_rwo[vi][bg][hk * Wk + wk][p] = tanhf(po[d]) * scl + rv;
    }
}

// =====================================================================
// Kernel 2: bilinear grid-sample of x (unchanged)
// =====================================================================
__global__ __launch_bounds__(256) void k_sample(const float* __restrict__ x)
{
    int cc = threadIdx.x & 63;
    int nsub = threadIdx.x >> 6;
    int n = blockIdx.x * 4 + nsub;
    int bg = blockIdx.y, vi = blockIdx.z;
    int b = bg / G, g = bg % G;

    float r0 = g_rwo[vi][bg][n][0];
    float r1 = g_rwo[vi][bg][n][1];
    float yp = (r0 + 1.f) * 0.5f * (float)(Hi - 1);
    float xp = (r1 + 1.f) * 0.5f * (float)(Wi - 1);
    float y0f = floorf(yp), x0f = floorf(xp);
    float fy = yp - y0f, fx = xp - x0f;
    int y0 = (int)y0f, x0 = (int)x0f;

    float wy0 = (y0     >= 0 && y0     <= Hi - 1) ? (1.f - fy) : 0.f;
    float wy1 = (y0 + 1 >= 0 && y0 + 1 <= Hi - 1) ? fy         : 0.f;
    float wx0 = (x0     >= 0 && x0     <= Wi - 1) ? (1.f - fx) : 0.f;
    float wx1 = (x0 + 1 >= 0 && x0 + 1 <= Wi - 1) ? fx         : 0.f;
    int iy0 = min(max(y0, 0), Hi - 1), iy1 = min(max(y0 + 1, 0), Hi - 1);
    int ix0 = min(max(x0, 0), Wi - 1), ix1 = min(max(x0 + 1, 0), Wi - 1);

    const float* img = x + (size_t)((b * V + vi) * C + g * CPG + cc) * (Hi * Wi);
    float val = wy0 * wx0 * img[iy0 * Wi + ix0]
              + wy0 * wx1 * img[iy0 * Wi + ix1]
              + wy1 * wx0 * img[iy1 * Wi + ix0]
              + wy1 * wx1 * img[iy1 * Wi + ix1];
    g_xs[vi][b][g * CPG + cc][n] = val;
}

// =====================================================================
// Kernel 3: K/V projection (unchanged)
// =====================================================================
__global__ __launch_bounds__(256) void k_proj(
    const float* __restrict__ kw, const float* __restrict__ kb,
    const float* __restrict__ vw, const float* __restrict__ vb)
{
    int n  = blockIdx.x * 256 + threadIdx.x;
    int o0 = blockIdx.y * 8;
    int z  = blockIdx.z;
    int kv = z & 1, b = (z >> 1) & 1, vi = z >> 2;
    const float* w    = kv ? vw : kw;
    const float* bias = kv ? vb : kb;

    __shared__ float sW[8][C];
    for (int idx = threadIdx.x; idx < 8 * C; idx += 256)
        sW[idx >> 7][idx & 127] = w[(o0 + (idx >> 7)) * C + (idx & 127)];
    __syncthreads();

    float acc[8];
#pragma unroll
    for (int oo = 0; oo < 8; oo++) acc[oo] = bias[o0 + oo];

    const float* xs = &g_xs[vi][b][0][0];
    for (int c = 0; c < C; c++) {
        float xv = xs[c * NS + n];
#pragma unroll
        for (int oo = 0; oo < 8; oo++) acc[oo] += sW[oo][c] * xv;
    }
    float* dst = kv ? &g_v[vi][b][0][0] : &g_k[vi][b][0][0];
#pragma unroll
    for (int oo = 0; oo < 8; oo++) dst[(o0 + oo) * NS + n] = acc[oo];
}

// =====================================================================
// Kernel 4: attention. 2-query tiling; K/V in channel-pair-interleaved
// float2 smem (conflict-free LDS.64, vectorized fill); FFMA2 hot loops.
// 128-thread blocks, 5 blocks/SM target for occupancy.
// =====================================================================
__global__ __launch_bounds__(128, 5) void k_attn(
    const float* __restrict__ query,
    const float* __restrict__ rpe_table)
{
    int warp = threadIdx.x >> 5, lane = threadIdx.x & 31, tid = threadIdx.x;
    int vi = blockIdx.z;
    int bh = blockIdx.y;
    int b = bh / NH, h = bh % NH;
    int g = h / HPG;
    int bg = b * G + g;

    int mp = blockIdx.x * 4 + warp;      // pair index 0..511
    int i0 = (mp >> 5) * 2;
    int j  = mp & 31;
    int m0 = i0 * 32 + j;
    int m1 = m0 + 32;

    // channel-pair interleaved: sK2[cp][n] = (K[2cp][n], K[2cp+1][n])
    __shared__ float2 sK2[CH / 2][256];
    __shared__ float2 sV2[CH / 2][256];
    __shared__ float sR0[256];
    __shared__ float sR1[256];

    // q packed as channel pairs
    unsigned long long qp0[CH / 2], qp1[CH / 2];
#pragma unroll
    for (int cp = 0; cp < CH / 2; cp++) {
        float a0 = query[(b * C + h * CH + 2 * cp) * M + m0];
        float b0 = query[(b * C + h * CH + 2 * cp + 1) * M + m0];
        float a1 = query[(b * C + h * CH + 2 * cp) * M + m1];
        float b1v = query[(b * C + h * CH + 2 * cp + 1) * M + m1];
        PACK2(qp0[cp], a0, b0);
        PACK2(qp1[cp], a1, b1v);
    }

    const float* rpe = rpe_table + h * RH * RW;
    const float* kbase = &g_k[vi][b][h * CH][0];
    const float* vbase = &g_v[vi][b][h * CH][0];

    float ml0 = -1e30f, ll0 = 0.f, ml1 = -1e30f, ll1 = 0.f;
    unsigned long long ap0[CH / 2], ap1[CH / 2];
    unsigned long long zero2; { PACK2(zero2, 0.f, 0.f); }
#pragma unroll
    for (int cp = 0; cp < CH / 2; cp++) { ap0[cp] = zero2; ap1[cp] = zero2; }

    float ybase = 15.5f + (float)i0;
    float xbase = 63.5f + (127.0f / 31.0f) * (float)j;

    for (int t = 0; t < NS / 256; t++) {
        __syncthreads();
        // vectorized interleaving fill: read float4 from rows 2cp and 2cp+1,
        // emit two interleaved float4 (= 4 float2 elements)
        for (int idx = tid; idx < (CH / 2) * 64; idx += 128) {
            int cp = idx >> 6, n4 = idx & 63;
            float4 ka = ((const float4*)(kbase + (2 * cp) * NS + t * 256))[n4];
            float4 kb4 = ((const float4*)(kbase + (2 * cp + 1) * NS + t * 256))[n4];
            ((float4*)&sK2[cp][0])[2 * n4]     = make_float4(ka.x, kb4.x, ka.y, kb4.y);
            ((float4*)&sK2[cp][0])[2 * n4 + 1] = make_float4(ka.z, kb4.z, ka.w, kb4.w);
            float4 va = ((const float4*)(vbase + (2 * cp) * NS + t * 256))[n4];
            float4 vb4 = ((const float4*)(vbase + (2 * cp + 1) * NS + t * 256))[n4];
            ((float4*)&sV2[cp][0])[2 * n4]     = make_float4(va.x, vb4.x, va.y, vb4.y);
            ((float4*)&sV2[cp][0])[2 * n4 + 1] = make_float4(va.z, vb4.z, va.w, vb4.w);
        }
        for (int idx = tid; idx < 256; idx += 128) {
            float2 rv = ((const float2*)&g_rwo[vi][bg][t * 256][0])[idx];
            sR0[idx] = rv.x;
            sR1[idx] = rv.y;
        }
        __syncthreads();

#pragma unroll 1
        for (int ch = 0; ch < 8; ch++) {
            int nl = ch * 32 + lane;

            // QK via packed channel pairs; base + immediate offsets
            const unsigned long long* kc = (const unsigned long long*)&sK2[0][nl];
            unsigned long long s0p = zero2, s1p = zero2;
#pragma unroll
            for (int cp = 0; cp < CH / 2; cp++) {
                unsigned long long kk = kc[cp * 256];
                FMA2(s0p, qp0[cp], kk, s0p);
                FMA2(s1p, qp1[cp], kk, s1p);
            }
            float s0a, s0b, s1a, s1b;
            UNPACK2(s0a, s0b, s0p);
            UNPACK2(s1a, s1b, s1p);
            float s0 = s0a + s0b, s1 = s1a + s1b;

            // --- shared bilinear rpe for the query pair ---
            float r0v = sR0[nl], r1v = sR1[nl];
            float xp = xbase - 63.5f * r1v;
            float x0f = floorf(xp);
            float fx = xp - x0f;
            int x0 = (int)x0f;
            float wx0 = (x0     >= 0 && x0     <= RW - 1) ? (1.f - fx) : 0.f;
            float wx1 = (x0 + 1 >= 0 && x0 + 1 <= RW - 1) ? fx         : 0.f;
            int ix0 = min(max(x0, 0), RW - 1), ix1 = min(max(x0 + 1, 0), RW - 1);

            float yp = ybase - 15.5f * r0v;
            float y0f = floorf(yp);
            float fy = yp - y0f;
            int y0 = (int)y0f;
            bool v0 = (y0     >= 0) && (y0     <= RH - 1);
            bool v1 = (y0 + 1 >= 0) && (y0 + 1 <= RH - 1);
            bool v2 = (y0 + 2 >= 0) && (y0 + 2 <= RH - 1);
            int cr0 = min(max(y0,     0), RH - 1);
            int cr1 = min(max(y0 + 1, 0), RH - 1);
            int cr2 = min(max(y0 + 2, 0), RH - 1);

            const float* p0r = rpe + cr0 * RW;
            const float* p1r = rpe + cr1 * RW;
            const float* p2r = rpe + cr2 * RW;
            float rc0 = wx0 * p0r[ix0] + wx1 * p0r[ix1];
            float rc1 = wx0 * p1r[ix0] + wx1 * p1r[ix1];
            float rc2 = wx0 * p2r[ix0] + wx1 * p2r[ix1];

            float wyA0 = v0 ? (1.f - fy) : 0.f;
            float wyA1 = v1 ? fy         : 0.f;
            float wyB0 = v1 ? (1.f - fy) : 0.f;
            float wyB1 = v2 ? fy         : 0.f;

            s0 = s0 * SCALE + wyA0 * rc0 + wyA1 * rc1;
            s1 = s1 * SCALE + wyB0 * rc1 + wyB1 * rc2;

            // --- per-lane online softmax ---
            if (s0 > ml0) {
                float sc = __expf(ml0 - s0);
                ll0 *= sc;
                unsigned long long scp; PACK2(scp, sc, sc);
#pragma unroll
                for (int cp = 0; cp < CH / 2; cp++) MUL2(ap0[cp], ap0[cp], scp);
                ml0 = s0;
            }
            float p0 = __expf(s0 - ml0);
            ll0 += p0;
            if (s1 > ml1) {
                float sc = __expf(ml1 - s1);
                ll1 *= sc;
                unsigned long long scp; PACK2(scp, sc, sc);
#pragma unroll
                for (int cp = 0; cp < CH / 2; cp++) MUL2(ap1[cp], ap1[cp], scp);
                ml1 = s1;
            }
            float p1 = __expf(s1 - ml1);
            ll1 += p1;

            unsigned long long p0p, p1p;
            PACK2(p0p, p0, p0);
            PACK2(p1p, p1, p1);
            const unsigned long long* vc = (const unsigned long long*)&sV2[0][nl];
#pragma unroll
            for (int cp = 0; cp < CH / 2; cp++) {
                unsigned long long vvp = vc[cp * 256];
                FMA2(ap0[cp], p0p, vvp, ap0[cp]);
                FMA2(ap1[cp], p1p, vvp, ap1[cp]);
            }
        }
    }

    // cross-lane reductions
    float gm0 = ml0, gm1 = ml1;
#pragma unroll
    for (int o = 16; o; o >>= 1) {
        gm0 = fmaxf(gm0, __shfl_xor_sync(0xffffffffu, gm0, o));
        gm1 = fmaxf(gm1, __shfl_xor_sync(0xffffffffu, gm1, o));
    }
    float f0 = __expf(ml0 - gm0), f1 = __expf(ml1 - gm1);
    float ls0 = ll0 * f0, ls1 = ll1 * f1;
#pragma unroll
    for (int o = 16; o; o >>= 1) {
        ls0 += __shfl_xor_sync(0xffffffffu, ls0, o);
        ls1 += __shfl_xor_sync(0xffffffffu, ls1, o);
    }
    float inv0 = 1.f / ls0, inv1 = 1.f / ls1;

#pragma unroll
    for (int cp = 0; cp < CH / 2; cp++) {
        float a0, b0, a1, b1v;
        UNPACK2(a0, b0, ap0[cp]);
        UNPACK2(a1, b1v, ap1[cp]);
        float o00 = a0 * f0, o01 = b0 * f0;
        float o10 = a1 * f1, o11 = b1v * f1;
#pragma unroll
        for (int q = 16; q; q >>= 1) {
            o00 += __shfl_xor_sync(0xffffffffu, o00, q);
            o01 += __shfl_xor_sync(0xffffffffu, o01, q);
            o10 += __shfl_xor_sync(0xffffffffu, o10, q);
            o11 += __shfl_xor_sync(0xffffffffu, o11, q);
        }
        if (lane == 0) {
            g_outcat[b][vi * C + h * CH + 2 * cp][m0]     = o00 * inv0;
            g_outcat[b][vi * C + h * CH + 2 * cp + 1][m0] = o01 * inv0;
            g_outcat[b][vi * C + h * CH + 2 * cp][m1]     = o10 * inv1;
            g_outcat[b][vi * C + h * CH + 2 * cp + 1][m1] = o11 * inv1;
        }
    }
}

// =====================================================================
// Kernel 5: output projection (unchanged)
// =====================================================================
__global__ __launch_bounds__(256) void k_out(
    const float* __restrict__ ow, const float* __restrict__ ob,
    float* __restrict__ out)
{
    int mm = blockIdx.x * 256 + threadIdx.x;
    int o0 = blockIdx.y * 8;
    int b  = blockIdx.z;

    __shared__ float sW[8][V * C];
    for (int idx = threadIdx.x; idx < 8 * V * C; idx += 256)
        sW[idx / (V * C)][idx % (V * C)] = ow[(o0 + idx / (V * C)) * (V * C) + (idx % (V * C))];
    __syncthreads();

    float acc[8];
#pragma unroll
    for (int oo = 0; oo < 8; oo++) acc[oo] = ob[o0 + oo];

    const float* src = &g_outcat[b][0][0];
    for (int c = 0; c < V * C; c++) {
        float xv = src[c * M + mm];
#pragma unroll
        for (int oo = 0; oo < 8; oo++) acc[oo] += sW[oo][c] * xv;
    }
#pragma unroll
    for (int oo = 0; oo < 8; oo++)
        out[(b * C + o0 + oo) * M + mm] = acc[oo];
}

// =====================================================================
extern "C" void kernel_launch(void* const* d_in, const int* in_sizes, int n_in,
                              void* d_out, int out_size)
{
    const float *x, *query, *refpts, *off_w1, *off_b1, *off_ln_g, *off_ln_b,
                *off_w2, *k_w, *k_b, *v_w, *v_b, *out_w, *out_b, *rpe;

    if (n_in >= 15 && in_sizes[0] == 3145728) {
        x        = (const float*)d_in[0];
        query    = (const float*)d_in[1];
        refpts   = (const float*)d_in[2];
        off_w1   = (const float*)d_in[3];
        off_b1   = (const float*)d_in[4];
        off_ln_g = (const float*)d_in[5];
        off_ln_b = (const float*)d_in[6];
        off_w2   = (const float*)d_in[7];
        k_w      = (const float*)d_in[8];
        k_b      = (const float*)d_in[9];
        v_w      = (const float*)d_in[10];
        v_b      = (const float*)d_in[11];
        out_w    = (const float*)d_in[12];
        out_b    = (const float*)d_in[13];
        rpe      = (const float*)d_in[14];
    } else {
        k_b      = (const float*)d_in[0];
        k_w      = (const float*)d_in[1];
        off_b1   = (const float*)d_in[2];
        off_ln_b = (const float*)d_in[3];
        off_ln_g = (const float*)d_in[4];
        off_w1   = (const float*)d_in[5];
        off_w2   = (const float*)d_in[6];
        out_b    = (const float*)d_in[7];
        out_w    = (const float*)d_in[8];
        query    = (const float*)d_in[9];
        refpts   = (const float*)d_in[10];
        rpe      = (const float*)d_in[11];
        v_b      = (const float*)d_in[12];
        v_w      = (const float*)d_in[13];
        x        = (const float*)d_in[14];
    }
    float* out = (float*)d_out;

    k_offset<<<dim3(M / 256, B * G, V), 256>>>(query, refpts, off_w1, off_b1,
                                               off_ln_g, off_ln_b, off_w2);
    k_sample<<<dim3(NS / 4, B * G, V), 256>>>(x);
    k_proj<<<dim3(NS / 256, C / 8, V * B * 2), 256>>>(k_w, k_b, v_w, v_b);
    k_attn<<<dim3(M / 2 / 4, B * NH, V), 128>>>(query, rpe);
    k_out<<<dim3(M / 256, C / 8, B), 256>>>(out_w, out_b, out);
}

// round 8
// speedup vs baseline: 1.9297x; 1.3973x over previous
#include <cuda_runtime.h>
#include <cuda_fp16.h>
#include <math.h>

// ---------------- problem constants ----------------
constexpr int B = 2, V = 3, G = 2, NH = 8, C = 128;
constexpr int CPG = C / G;       // 64
constexpr int CH  = C / NH;      // 16
constexpr int HPG = NH / G;      // 4
constexpr int Hq = 32, Wq = 32, M = Hq * Wq;   // 1024
constexpr int D = 4;
constexpr int Hk = Hq / 2, Wk = Wq * D;        // 16, 128
constexpr int NS = Hk * Wk;                    // 2048
constexpr int Hi = 64, Wi = 64;
constexpr int RH = Hq * 2 - 1;   // 63
constexpr int RW = Wq * D * 2 - 1; // 255
constexpr float SCALE = 0.25f;
constexpr float OFR = 5.0f;
constexpr float EPS = 1e-5f;
constexpr int RPE_ROWS = 45;     // max rows window per i0 (yp in [i0-5.2, i0+36.2] +2)

// packed f32x2 helpers
#define FMA2(d, a, b, c) asm("fma.rn.f32x2 %0, %1, %2, %3;" : "=l"(d) : "l"(a), "l"(b), "l"(c))
#define MUL2(d, a, b)    asm("mul.rn.f32x2 %0, %1, %2;"     : "=l"(d) : "l"(a), "l"(b))
#define PACK2(d, lo, hi) asm("mov.b64 %0, {%1, %2};"        : "=l"(d) : "f"(lo), "f"(hi))
#define UNPACK2(lo, hi, v) asm("mov.b64 {%0, %1}, %2;"      : "=f"(lo), "=f"(hi) : "l"(v))

// ---------------- scratch ----------------
__device__ float g_rwo[V][B * G][NS][2];
__device__ float g_xs[V][B][C][NS];
__device__ float g_k[V][B][C][NS];
__device__ float g_v[V][B][C][NS];
__device__ float g_outcat[B][V * C][M];

// =====================================================================
// Kernel 1: offset net (unchanged — correct)
// =====================================================================
__global__ __launch_bounds__(256) void k_offset(
    const float* __restrict__ query,
    const float* __restrict__ refpts,
    const float* __restrict__ w1,
    const float* __restrict__ b1,
    const float* __restrict__ lng,
    const float* __restrict__ lnb,
    const float* __restrict__ w2)
{
    int pix = blockIdx.x * 256 + threadIdx.x;
    int bg = blockIdx.y, vi = blockIdx.z;
    int b = bg / G, g = bg % G;
    int y = pix >> 5, x = pix & 31;

    const float* W1 = w1 + vi * 256;
    const float* B1 = b1 + vi * 256;
    const float* LG = lng + vi * 256;
    const float* LB = lnb + vi * 256;
    const float* W2 = w2 + vi * 4 * 256;

    float s = 0.f, ss = 0.f;
    for (int c = 0; c < CPG; c++) {
        float qv = query[((b * C + g * CPG + c) * Hq + y) * Wq + x];
#pragma unroll
        for (int d = 0; d < 4; d++) {
            int cd = c * 4 + d;
            float hv = qv * W1[cd] + B1[cd];
            s += hv; ss += hv * hv;
        }
    }
    float mu  = s * (1.f / 256.f);
    float var = ss * (1.f / 256.f) - mu * mu;
    float rs  = rsqrtf(var + EPS);

    float po[4] = {0.f, 0.f, 0.f, 0.f};
    for (int c = 0; c < CPG; c++) {
        float qv = query[((b * C + g * CPG + c) * Hq + y) * Wq + x];
#pragma unroll
        for (int d = 0; d < 4; d++) {
            int cd = c * 4 + d;
            float hv = qv * W1[cd] + B1[cd];
            float hn = (hv - mu) * rs * LG[cd] + LB[cd];
            float ge = 0.5f * hn * (1.f + erff(hn * 0.70710678118654752f));
#pragma unroll
            for (int d2 = 0; d2 < 4; d2++)
                po[d2] += ge * W2[d2 * 256 + cd];
        }
    }

    int p = y & 1, hk = y >> 1;
    float scl = (p == 0) ? (OFR / (float)(Hk - 1)) : (OFR / (float)(Wk - 1));
#pragma unroll
    for (int d = 0; d < 4; d++) {
        int wk = x * 4 + d;
        float rv = refpts[(((b * V + vi) * Hk + hk) * Wk + wk) * 2 + (1 - p)];
        g_rwo[vi][bg][hk * Wk + wk][p] = tanhf(po[d]) * scl + rv;
    }
}

// =====================================================================
// Kernel 2: bilinear grid-sample of x (unchanged)
// =====================================================================
__global__ __launch_bounds__(256) void k_sample(const float* __restrict__ x)
{
    int cc = threadIdx.x & 63;
    int nsub = threadIdx.x >> 6;
    int n = blockIdx.x * 4 + nsub;
    int bg = blockIdx.y, vi = blockIdx.z;
    int b = bg / G, g = bg % G;

    float r0 = g_rwo[vi][bg][n][0];
    float r1 = g_rwo[vi][bg][n][1];
    float yp = (r0 + 1.f) * 0.5f * (float)(Hi - 1);
    float xp = (r1 + 1.f) * 0.5f * (float)(Wi - 1);
    float y0f = floorf(yp), x0f = floorf(xp);
    float fy = yp - y0f, fx = xp - x0f;
    int y0 = (int)y0f, x0 = (int)x0f;

    float wy0 = (y0     >= 0 && y0     <= Hi - 1) ? (1.f - fy) : 0.f;
    float wy1 = (y0 + 1 >= 0 && y0 + 1 <= Hi - 1) ? fy         : 0.f;
    float wx0 = (x0     >= 0 && x0     <= Wi - 1) ? (1.f - fx) : 0.f;
    float wx1 = (x0 + 1 >= 0 && x0 + 1 <= Wi - 1) ? fx         : 0.f;
    int iy0 = min(max(y0, 0), Hi - 1), iy1 = min(max(y0 + 1, 0), Hi - 1);
    int ix0 = min(max(x0, 0), Wi - 1), ix1 = min(max(x0 + 1, 0), Wi - 1);

    const float* img = x + (size_t)((b * V + vi) * C + g * CPG + cc) * (Hi * Wi);
    float val = wy0 * wx0 * img[iy0 * Wi + ix0]
              + wy0 * wx1 * img[iy0 * Wi + ix1]
              + wy1 * wx0 * img[iy1 * Wi + ix0]
              + wy1 * wx1 * img[iy1 * Wi + ix1];
    g_xs[vi][b][g * CPG + cc][n] = val;
}

// =====================================================================
// Kernel 3: K/V projection (unchanged)
// =====================================================================
__global__ __launch_bounds__(256) void k_proj(
    const float* __restrict__ kw, const float* __restrict__ kb,
    const float* __restrict__ vw, const float* __restrict__ vb)
{
    int n  = blockIdx.x * 256 + threadIdx.x;
    int o0 = blockIdx.y * 8;
    int z  = blockIdx.z;
    int kv = z & 1, b = (z >> 1) & 1, vi = z >> 2;
    const float* w    = kv ? vw : kw;
    const float* bias = kv ? vb : kb;

    __shared__ float sW[8][C];
    for (int idx = threadIdx.x; idx < 8 * C; idx += 256)
        sW[idx >> 7][idx & 127] = w[(o0 + (idx >> 7)) * C + (idx & 127)];
    __syncthreads();

    float acc[8];
#pragma unroll
    for (int oo = 0; oo < 8; oo++) acc[oo] = bias[o0 + oo];

    const float* xs = &g_xs[vi][b][0][0];
    for (int c = 0; c < C; c++) {
        float xv = xs[c * NS + n];
#pragma unroll
        for (int oo = 0; oo < 8; oo++) acc[oo] += sW[oo][c] * xv;
    }
    float* dst = kv ? &g_v[vi][b][0][0] : &g_k[vi][b][0][0];
#pragma unroll
    for (int oo = 0; oo < 8; oo++) dst[(o0 + oo) * NS + n] = acc[oo];
}

// =====================================================================
// Kernel 4: attention. 256-thread blocks (8 warps share tile fill);
// 2-query tiling; FFMA2 channel-pair hot loop; rpe table rows cached in
// fp16 smem -> scattered gathers become cheap LDS.16 instead of LDG.
// All warps in a block share the same i0 (row pair), so one 45-row rpe
// window serves the whole block.
// =====================================================================
__global__ __launch_bounds__(256, 2) void k_attn(
    const float* __restrict__ query,
    const float* __restrict__ rpe_table)
{
    int warp = threadIdx.x >> 5, lane = threadIdx.x & 31, tid = threadIdx.x;
    int vi = blockIdx.z;
    int bh = blockIdx.y;
    int b = bh / NH, h = bh % NH;
    int g = h / HPG;
    int bg = b * G + g;

    int mp = blockIdx.x * 8 + warp;      // pair index 0..511
    int i0 = (mp >> 5) * 2;              // same for all warps in a block
    int j  = mp & 31;
    int m0 = i0 * 32 + j;
    int m1 = m0 + 32;

    // channel-pair interleaved: sK2[cp][n] = (K[2cp][n], K[2cp+1][n])
    __shared__ float2 sK2[CH / 2][256];
    __shared__ float2 sV2[CH / 2][256];
    __shared__ float sR0[256];
    __shared__ float sR1[256];
    __shared__ __half sRpe[RPE_ROWS][256];

    // rpe row window for this block's i0
    int r_lo = max(0, i0 - 6);
    int r_hi = min(RH - 1, i0 + 38);
    int nrows = r_hi - r_lo + 1;         // <= 45

    const float* rpe = rpe_table + h * RH * RW;
    // fill rpe window once (fp32 -> fp16)
    for (int idx = tid; idx < nrows * 256; idx += 256) {
        int r = idx >> 8, cx = idx & 255;
        if (cx < RW)
            sRpe[r][cx] = __float2half(rpe[(r_lo + r) * RW + cx]);
    }

    // q packed as channel pairs
    unsigned long long qp0[CH / 2], qp1[CH / 2];
#pragma unroll
    for (int cp = 0; cp < CH / 2; cp++) {
        float a0 = query[(b * C + h * CH + 2 * cp) * M + m0];
        float b0 = query[(b * C + h * CH + 2 * cp + 1) * M + m0];
        float a1 = query[(b * C + h * CH + 2 * cp) * M + m1];
        float b1v = query[(b * C + h * CH + 2 * cp + 1) * M + m1];
        PACK2(qp0[cp], a0, b0);
        PACK2(qp1[cp], a1, b1v);
    }

    const float* kbase = &g_k[vi][b][h * CH][0];
    const float* vbase = &g_v[vi][b][h * CH][0];

    float ml0 = -1e30f, ll0 = 0.f, ml1 = -1e30f, ll1 = 0.f;
    unsigned long long ap0[CH / 2], ap1[CH / 2];
    unsigned long long zero2; { PACK2(zero2, 0.f, 0.f); }
#pragma unroll
    for (int cp = 0; cp < CH / 2; cp++) { ap0[cp] = zero2; ap1[cp] = zero2; }

    float ybase = 15.5f + (float)i0;
    float xbase = 63.5f + (127.0f / 31.0f) * (float)j;

    for (int t = 0; t < NS / 256; t++) {
        __syncthreads();
        // vectorized interleaving fill (8 warps share the tile)
        for (int idx = tid; idx < (CH / 2) * 64; idx += 256) {
            int cp = idx >> 6, n4 = idx & 63;
            float4 ka = ((const float4*)(kbase + (2 * cp) * NS + t * 256))[n4];
            float4 kb4 = ((const float4*)(kbase + (2 * cp + 1) * NS + t * 256))[n4];
            ((float4*)&sK2[cp][0])[2 * n4]     = make_float4(ka.x, kb4.x, ka.y, kb4.y);
            ((float4*)&sK2[cp][0])[2 * n4 + 1] = make_float4(ka.z, kb4.z, ka.w, kb4.w);
            float4 va = ((const float4*)(vbase + (2 * cp) * NS + t * 256))[n4];
            float4 vb4 = ((const float4*)(vbase + (2 * cp + 1) * NS + t * 256))[n4];
            ((float4*)&sV2[cp][0])[2 * n4]     = make_float4(va.x, vb4.x, va.y, vb4.y);
            ((float4*)&sV2[cp][0])[2 * n4 + 1] = make_float4(va.z, vb4.z, va.w, vb4.w);
        }
        for (int idx = tid; idx < 256; idx += 256) {
            float2 rv = ((const float2*)&g_rwo[vi][bg][t * 256][0])[idx];
            sR0[idx] = rv.x;
            sR1[idx] = rv.y;
        }
        __syncthreads();

#pragma unroll 1
        for (int ch = 0; ch < 8; ch++) {
            int nl = ch * 32 + lane;

            // QK via packed channel pairs
            const unsigned long long* kc = (const unsigned long long*)&sK2[0][nl];
            unsigned long long s0p = zero2, s1p = zero2;
#pragma unroll
            for (int cp = 0; cp < CH / 2; cp++) {
                unsigned long long kk = kc[cp * 256];
                FMA2(s0p, qp0[cp], kk, s0p);
                FMA2(s1p, qp1[cp], kk, s1p);
            }
            float s0a, s0b, s1a, s1b;
            UNPACK2(s0a, s0b, s0p);
            UNPACK2(s1a, s1b, s1p);
            float s0 = s0a + s0b, s1 = s1a + s1b;

            // --- shared bilinear rpe for the query pair (smem gathers) ---
            float r0v = sR0[nl], r1v = sR1[nl];
            float xp = xbase - 63.5f * r1v;
            float x0f = floorf(xp);
            float fx = xp - x0f;
            int x0 = (int)x0f;
            float wx0 = (x0     >= 0 && x0     <= RW - 1) ? (1.f - fx) : 0.f;
            float wx1 = (x0 + 1 >= 0 && x0 + 1 <= RW - 1) ? fx         : 0.f;
            int ix0 = min(max(x0, 0), RW - 1), ix1 = min(max(x0 + 1, 0), RW - 1);

            float yp = ybase - 15.5f * r0v;
            float y0f = floorf(yp);
            float fy = yp - y0f;
            int y0 = (int)y0f;
            bool v0 = (y0     >= 0) && (y0     <= RH - 1);
            bool v1 = (y0 + 1 >= 0) && (y0 + 1 <= RH - 1);
            bool v2 = (y0 + 2 >= 0) && (y0 + 2 <= RH - 1);
            int cr0 = min(max(y0,     0), RH - 1) - r_lo;
            int cr1 = min(max(y0 + 1, 0), RH - 1) - r_lo;
            int cr2 = min(max(y0 + 2, 0), RH - 1) - r_lo;

            const __half* p0r = &sRpe[cr0][0];
            const __half* p1r = &sRpe[cr1][0];
            const __half* p2r = &sRpe[cr2][0];
            float rc0 = wx0 * __half2float(p0r[ix0]) + wx1 * __half2float(p0r[ix1]);
            float rc1 = wx0 * __half2float(p1r[ix0]) + wx1 * __half2float(p1r[ix1]);
            float rc2 = wx0 * __half2float(p2r[ix0]) + wx1 * __half2float(p2r[ix1]);

            float wyA0 = v0 ? (1.f - fy) : 0.f;
            float wyA1 = v1 ? fy         : 0.f;
            float wyB0 = v1 ? (1.f - fy) : 0.f;
            float wyB1 = v2 ? fy         : 0.f;

            s0 = s0 * SCALE + wyA0 * rc0 + wyA1 * rc1;
            s1 = s1 * SCALE + wyB0 * rc1 + wyB1 * rc2;

            // --- per-lane online softmax ---
            if (s0 > ml0) {
                float sc = __expf(ml0 - s0);
                ll0 *= sc;
                unsigned long long scp; PACK2(scp, sc, sc);
#pragma unroll
                for (int cp = 0; cp < CH / 2; cp++) MUL2(ap0[cp], ap0[cp], scp);
                ml0 = s0;
            }
            float p0 = __expf(s0 - ml0);
            ll0 += p0;
            if (s1 > ml1) {
                float sc = __expf(ml1 - s1);
                ll1 *= sc;
                unsigned long long scp; PACK2(scp, sc, sc);
#pragma unroll
                for (int cp = 0; cp < CH / 2; cp++) MUL2(ap1[cp], ap1[cp], scp);
                ml1 = s1;
            }
            float p1 = __expf(s1 - ml1);
            ll1 += p1;

            unsigned long long p0p, p1p;
            PACK2(p0p, p0, p0);
            PACK2(p1p, p1, p1);
            const unsigned long long* vc = (const unsigned long long*)&sV2[0][nl];
#pragma unroll
            for (int cp = 0; cp < CH / 2; cp++) {
                unsigned long long vvp = vc[cp * 256];
                FMA2(ap0[cp], p0p, vvp, ap0[cp]);
                FMA2(ap1[cp], p1p, vvp, ap1[cp]);
            }
        }
    }

    // cross-lane reductions
    float gm0 = ml0, gm1 = ml1;
#pragma unroll
    for (int o = 16; o; o >>= 1) {
        gm0 = fmaxf(gm0, __shfl_xor_sync(0xffffffffu, gm0, o));
        gm1 = fmaxf(gm1, __shfl_xor_sync(0xffffffffu, gm1, o));
    }
    float f0 = __expf(ml0 - gm0), f1 = __expf(ml1 - gm1);
    float ls0 = ll0 * f0, ls1 = ll1 * f1;
#pragma unroll
    for (int o = 16; o; o >>= 1) {
        ls0 += __shfl_xor_sync(0xffffffffu, ls0, o);
        ls1 += __shfl_xor_sync(0xffffffffu, ls1, o);
    }
    float inv0 = 1.f / ls0, inv1 = 1.f / ls1;

#pragma unroll
    for (int cp = 0; cp < CH / 2; cp++) {
        float a0, b0, a1, b1v;
        UNPACK2(a0, b0, ap0[cp]);
        UNPACK2(a1, b1v, ap1[cp]);
        float o00 = a0 * f0, o01 = b0 * f0;
        float o10 = a1 * f1, o11 = b1v * f1;
#pragma unroll
        for (int q = 16; q; q >>= 1) {
            o00 += __shfl_xor_sync(0xffffffffu, o00, q);
            o01 += __shfl_xor_sync(0xffffffffu, o01, q);
            o10 += __shfl_xor_sync(0xffffffffu, o10, q);
            o11 += __shfl_xor_sync(0xffffffffu, o11, q);
        }
        if (lane == 0) {
            g_outcat[b][vi * C + h * CH + 2 * cp][m0]     = o00 * inv0;
            g_outcat[b][vi * C + h * CH + 2 * cp + 1][m0] = o01 * inv0;
            g_outcat[b][vi * C + h * CH + 2 * cp][m1]     = o10 * inv1;
            g_outcat[b][vi * C + h * CH + 2 * cp + 1][m1] = o11 * inv1;
        }
    }
}

// =====================================================================
// Kernel 5: output projection (unchanged)
// =====================================================================
__global__ __launch_bounds__(256) void k_out(
    const float* __restrict__ ow, const float* __restrict__ ob,
    float* __restrict__ out)
{
    int mm = blockIdx.x * 256 + threadIdx.x;
    int o0 = blockIdx.y * 8;
    int b  = blockIdx.z;

    __shared__ float sW[8][V * C];
    for (int idx = threadIdx.x; idx < 8 * V * C; idx += 256)
        sW[idx / (V * C)][idx % (V * C)] = ow[(o0 + idx / (V * C)) * (V * C) + (idx % (V * C))];
    __syncthreads();

    float acc[8];
#pragma unroll
    for (int oo = 0; oo < 8; oo++) acc[oo] = ob[o0 + oo];

    const float* src = &g_outcat[b][0][0];
    for (int c = 0; c < V * C; c++) {
        float xv = src[c * M + mm];
#pragma unroll
        for (int oo = 0; oo < 8; oo++) acc[oo] += sW[oo][c] * xv;
    }
#pragma unroll
    for (int oo = 0; oo < 8; oo++)
        out[(b * C + o0 + oo) * M + mm] = acc[oo];
}

// =====================================================================
extern "C" void kernel_launch(void* const* d_in, const int* in_sizes, int n_in,
                              void* d_out, int out_size)
{
    const float *x, *query, *refpts, *off_w1, *off_b1, *off_ln_g, *off_ln_b,
                *off_w2, *k_w, *k_b, *v_w, *v_b, *out_w, *out_b, *rpe;

    if (n_in >= 15 && in_sizes[0] == 3145728) {
        x        = (const float*)d_in[0];
        query    = (const float*)d_in[1];
        refpts   = (const float*)d_in[2];
        off_w1   = (const float*)d_in[3];
        off_b1   = (const float*)d_in[4];
        off_ln_g = (const float*)d_in[5];
        off_ln_b = (const float*)d_in[6];
        off_w2   = (const float*)d_in[7];
        k_w      = (const float*)d_in[8];
        k_b      = (const float*)d_in[9];
        v_w      = (const float*)d_in[10];
        v_b      = (const float*)d_in[11];
        out_w    = (const float*)d_in[12];
        out_b    = (const float*)d_in[13];
        rpe      = (const float*)d_in[14];
    } else {
        k_b      = (const float*)d_in[0];
        k_w      = (const float*)d_in[1];
        off_b1   = (const float*)d_in[2];
        off_ln_b = (const float*)d_in[3];
        off_ln_g = (const float*)d_in[4];
        off_w1   = (const float*)d_in[5];
        off_w2   = (const float*)d_in[6];
        out_b    = (const float*)d_in[7];
        out_w    = (const float*)d_in[8];
        query    = (const float*)d_in[9];
        refpts   = (const float*)d_in[10];
        rpe      = (const float*)d_in[11];
        v_b      = (const float*)d_in[12];
        v_w      = (const float*)d_in[13];
        x        = (const float*)d_in[14];
    }
    float* out = (float*)d_out;

    k_offset<<<dim3(M / 256, B * G, V), 256>>>(query, refpts, off_w1, off_b1,
                                               off_ln_g, off_ln_b, off_w2);
    k_sample<<<dim3(NS / 4, B * G, V), 256>>>(x);
    k_proj<<<dim3(NS / 256, C / 8, V * B * 2), 256>>>(k_w, k_b, v_w, v_b);
    k_attn<<<dim3(M / 2 / 8, B * NH, V), 256>>>(query, rpe);
    k_out<<<dim3(M / 256, C / 8, B), 256>>>(out_w, out_b, out);
}